// round 9
// baseline (speedup 1.0000x reference)
#include <cuda_runtime.h>
#include <cstdint>

#define T_SEQ 128
#define BATCH 512
#define DIM   128
#define NQ    8
#define NCH   32   // 4 gates * 8 wires

typedef unsigned long long u64;

// Scratch: zpre[(t*BATCH+b)*32 + ch] = x_t[b] @ Wx[:,ch], ch = gate*8+wire
__device__ float g_zpre[(size_t)T_SEQ * BATCH * NCH];
// dump target for lanes that don't own an output slot (never read)
__device__ float g_dump[64];

__device__ __forceinline__ float tanh_approx(float x) {
    float r;
    asm("tanh.approx.f32 %0, %1;" : "=f"(r) : "f"(x));
    return r;
}
__device__ __forceinline__ void ffma2(u64& acc, u64 a, u64 b) {
    asm("fma.rn.f32x2 %0, %1, %2, %0;" : "+l"(acc) : "l"(a), "l"(b));
}
__device__ __forceinline__ u64 add2(u64 a, u64 b) {
    u64 r; asm("add.rn.f32x2 %0, %1, %2;" : "=l"(r) : "l"(a), "l"(b)); return r;
}
__device__ __forceinline__ u64 pack2(float lo, float hi) {
    u64 r; asm("mov.b64 %0, {%1, %2};" : "=l"(r) : "f"(lo), "f"(hi)); return r;
}
__device__ __forceinline__ void unpack2(float& lo, float& hi, u64 v) {
    asm("mov.b64 {%0, %1}, %2;" : "=f"(lo), "=f"(hi) : "l"(v));
}

// ---------------------------------------------------------------------------
// Kernel A (proven, ~7.7us): zpre = X @ Wx via packed f32x2 FMA.
// ---------------------------------------------------------------------------
__global__ void __launch_bounds__(128) qlstm_gemm(
    const float* __restrict__ x,
    const float* __restrict__ Wf, const float* __restrict__ Wi,
    const float* __restrict__ Wu, const float* __restrict__ Wo)
{
    __shared__ __align__(16) float ws[128][32];
    __shared__ float xs[32][129];
    const int tid  = threadIdx.x;
    const int row0 = blockIdx.x * 128;

    #pragma unroll 4
    for (int i = tid; i < 128 * 32; i += 128) {
        int k = i >> 5, j = i & 31;
        int g = j >> 3, w = j & 7;
        const float* Wg = (g == 0) ? Wf : (g == 1) ? Wi : (g == 2) ? Wu : Wo;
        ws[k][j] = Wg[k * 8 + w];
    }

    const int lane = tid & 31;
    const int c0   = (tid >> 5) * 8;

    u64 acc[4][4];
    #pragma unroll
    for (int r = 0; r < 4; r++)
        #pragma unroll
        for (int q = 0; q < 4; q++) acc[r][q] = 0ull;

    for (int kc = 0; kc < 4; ++kc) {
        __syncthreads();
        #pragma unroll 4
        for (int i = tid; i < 128 * 32; i += 128) {
            int r = i >> 5, kk = i & 31;
            xs[kk][r] = x[(size_t)(row0 + r) * DIM + kc * 32 + kk];
        }
        __syncthreads();

        #pragma unroll
        for (int k = 0; k < 32; ++k) {
            float xv0 = xs[k][lane      ];
            float xv1 = xs[k][lane + 32 ];
            float xv2 = xs[k][lane + 64 ];
            float xv3 = xs[k][lane + 96 ];
            u64 xx0 = pack2(xv0, xv0);
            u64 xx1 = pack2(xv1, xv1);
            u64 xx2 = pack2(xv2, xv2);
            u64 xx3 = pack2(xv3, xv3);
            const u64* wk = reinterpret_cast<const u64*>(&ws[kc * 32 + k][c0]);
            u64 w0 = wk[0], w1 = wk[1], w2 = wk[2], w3 = wk[3];
            ffma2(acc[0][0], xx0, w0); ffma2(acc[0][1], xx0, w1);
            ffma2(acc[0][2], xx0, w2); ffma2(acc[0][3], xx0, w3);
            ffma2(acc[1][0], xx1, w0); ffma2(acc[1][1], xx1, w1);
            ffma2(acc[1][2], xx1, w2); ffma2(acc[1][3], xx1, w3);
            ffma2(acc[2][0], xx2, w0); ffma2(acc[2][1], xx2, w1);
            ffma2(acc[2][2], xx2, w2); ffma2(acc[2][3], xx2, w3);
            ffma2(acc[3][0], xx3, w0); ffma2(acc[3][1], xx3, w1);
            ffma2(acc[3][2], xx3, w2); ffma2(acc[3][3], xx3, w3);
        }
    }

    #pragma unroll
    for (int rr = 0; rr < 4; ++rr) {
        int r = row0 + lane + 32 * rr;
        u64* dst = reinterpret_cast<u64*>(g_zpre + (size_t)r * NCH + c0);
        dst[0] = acc[rr][0]; dst[1] = acc[rr][1];
        dst[2] = acc[rr][2]; dst[3] = acc[rr][3];
    }
}

// ---------------------------------------------------------------------------
// Kernel B: recurrence, one warp per row; only 10 SHFLs per step.
// Lane (g,w) computes ALL 8 z/cos of its gate locally (8x8 weight block in
// packed registers, wire-pair FFMA2), so no cosine allgather. h reaches every
// lane via a 7-shfl xor-butterfly (weights pre-permuted to arrival order);
// cross-gate act gather is a 3-shfl butterfly + FSEL muxes.
// <Z_w> = prod_{k<=w} cos(phi_k) (w>=1), <Z_0> = prod_{k=1..7} cos(phi_k).
// ---------------------------------------------------------------------------
__global__ void __launch_bounds__(128) qlstm_recurrent(
    const float* __restrict__ Wf, const float* __restrict__ bf, const float* __restrict__ thf,
    const float* __restrict__ Wi, const float* __restrict__ bi, const float* __restrict__ thi,
    const float* __restrict__ Wu, const float* __restrict__ bu, const float* __restrict__ thu,
    const float* __restrict__ Wo, const float* __restrict__ bo, const float* __restrict__ tho,
    float* __restrict__ out)
{
    const int lane = threadIdx.x & 31;
    const int warp = threadIdx.x >> 5;
    const int row  = blockIdx.x * 4 + warp;       // 0..511
    const int gate = lane >> 3;
    const int wire = lane & 7;

    const float* Wg = (gate == 0) ? Wf : (gate == 1) ? Wi : (gate == 2) ? Wu : Wo;
    const float* bg = (gate == 0) ? bf : (gate == 1) ? bi : (gate == 2) ? bu : bo;
    const float* tg = (gate == 0) ? thf : (gate == 1) ? thi : (gate == 2) ? thu : tho;

    // butterfly arrival order: slot j holds h_{wire ^ m[j]}
    const int m[8] = {0, 4, 2, 6, 1, 5, 3, 7};

    // weight pairs: wpk[j][p] = ( Wh[k_j][2p], Wh[k_j][2p+1] ), k_j = wire^m[j]
    u64 wpk[8][4];
    #pragma unroll
    for (int j = 0; j < 8; ++j) {
        int kj = wire ^ m[j];
        #pragma unroll
        for (int p = 0; p < 4; ++p)
            wpk[j][p] = pack2(Wg[(DIM + kj) * NQ + 2 * p],
                              Wg[(DIM + kj) * NQ + 2 * p + 1]);
    }
    // combined bias pairs
    u64 cbz[4];
    #pragma unroll
    for (int p = 0; p < 4; ++p)
        cbz[p] = pack2(bg[2 * p] + tg[2 * p], bg[2 * p + 1] + tg[2 * p + 1]);

    const bool  isU  = (gate == 2);
    const float aScl = isU ? 1.0f : 0.5f;
    const float aMul = isU ? 1.0f : 0.5f;
    const float aAdd = isU ? 0.0f : 0.5f;

    const bool p0 = (wire & 1) != 0;
    const bool p1 = (wire & 2) != 0;
    const bool p2 = (wire & 4) != 0;
    const bool gb0 = (gate & 1) != 0;
    const bool gb1 = (gate & 2) != 0;

    float hv = 0.0f, cstate = 0.0f;

    // zpre: this lane reads its gate's 8 channels (two float4s) each step
    const float4* zq = reinterpret_cast<const float4*>(
        g_zpre + (size_t)row * NCH + gate * 8);
    const size_t zstr4 = (size_t)BATCH * NCH / 4;    // float4 stride per step
    float4 cur0 = zq[0],       cur1 = zq[1];
    float4 nx0  = zq[zstr4],   nx1  = zq[zstr4 + 1];

    // branch-free output pointer
    float* st = (lane < 8) ? (out + (size_t)row * NQ + wire) : (g_dump + lane);
    const size_t sstr = (lane < 8) ? (size_t)(BATCH * NQ) : 0;

    const unsigned FULL = 0xffffffffu;

    #pragma unroll 1
    for (int t = 0; t < T_SEQ; ++t) {
        // acc[p] = zpre pair + bias pair
        u64 acc0 = add2(pack2(cur0.x, cur0.y), cbz[0]);
        u64 acc1 = add2(pack2(cur0.z, cur0.w), cbz[1]);
        u64 acc2 = add2(pack2(cur1.x, cur1.y), cbz[2]);
        u64 acc3 = add2(pack2(cur1.z, cur1.w), cbz[3]);

        cur0 = nx0; cur1 = nx1;
        int t2 = (t + 2 < T_SEQ) ? (t + 2) : (T_SEQ - 1);
        nx0 = zq[(size_t)t2 * zstr4];
        nx1 = zq[(size_t)t2 * zstr4 + 1];

        // --- h butterfly: 7 shfls, slots in order m = [0,4,2,6,1,5,3,7] ---
        float hs0 = hv;
        float hs1 = __shfl_xor_sync(FULL, hs0, 4);
        float hs2 = __shfl_xor_sync(FULL, hs0, 2);
        float hs3 = __shfl_xor_sync(FULL, hs1, 2);
        float hs4 = __shfl_xor_sync(FULL, hs0, 1);
        float hs5 = __shfl_xor_sync(FULL, hs1, 1);
        float hs6 = __shfl_xor_sync(FULL, hs2, 1);
        float hs7 = __shfl_xor_sync(FULL, hs3, 1);

        // --- z for all 8 wires of this gate: 32 FFMA2 (wire-pair packed) ---
        u64 hd;
        hd = pack2(hs0, hs0);
        ffma2(acc0, hd, wpk[0][0]); ffma2(acc1, hd, wpk[0][1]);
        ffma2(acc2, hd, wpk[0][2]); ffma2(acc3, hd, wpk[0][3]);
        hd = pack2(hs1, hs1);
        ffma2(acc0, hd, wpk[1][0]); ffma2(acc1, hd, wpk[1][1]);
        ffma2(acc2, hd, wpk[1][2]); ffma2(acc3, hd, wpk[1][3]);
        hd = pack2(hs2, hs2);
        ffma2(acc0, hd, wpk[2][0]); ffma2(acc1, hd, wpk[2][1]);
        ffma2(acc2, hd, wpk[2][2]); ffma2(acc3, hd, wpk[2][3]);
        hd = pack2(hs3, hs3);
        ffma2(acc0, hd, wpk[3][0]); ffma2(acc1, hd, wpk[3][1]);
        ffma2(acc2, hd, wpk[3][2]); ffma2(acc3, hd, wpk[3][3]);
        hd = pack2(hs4, hs4);
        ffma2(acc0, hd, wpk[4][0]); ffma2(acc1, hd, wpk[4][1]);
        ffma2(acc2, hd, wpk[4][2]); ffma2(acc3, hd, wpk[4][3]);
        hd = pack2(hs5, hs5);
        ffma2(acc0, hd, wpk[5][0]); ffma2(acc1, hd, wpk[5][1]);
        ffma2(acc2, hd, wpk[5][2]); ffma2(acc3, hd, wpk[5][3]);
        hd = pack2(hs6, hs6);
        ffma2(acc0, hd, wpk[6][0]); ffma2(acc1, hd, wpk[6][1]);
        ffma2(acc2, hd, wpk[6][2]); ffma2(acc3, hd, wpk[6][3]);
        hd = pack2(hs7, hs7);
        ffma2(acc0, hd, wpk[7][0]); ffma2(acc1, hd, wpk[7][1]);
        ffma2(acc2, hd, wpk[7][2]); ffma2(acc3, hd, wpk[7][3]);

        // --- cosines of all 8 wires (local, no exchange) ---
        float z0, z1, z2, z3, z4, z5, z6, z7;
        unpack2(z0, z1, acc0);
        unpack2(z2, z3, acc1);
        unpack2(z4, z5, acc2);
        unpack2(z6, z7, acc3);
        float cc0 = __cosf(z0), cc1 = __cosf(z1);
        float cc2 = __cosf(z2), cc3 = __cosf(z3);
        float cc4 = __cosf(z4), cc5 = __cosf(z5);
        float cc6 = __cosf(z6), cc7 = __cosf(z7);

        // prefix products (Sklansky) + own-wire mux
        float m01 = cc0*cc1, m23 = cc2*cc3, m45 = cc4*cc5, m67 = cc6*cc7;
        float m0123 = m01*m23, m4567 = m45*m67;
        float P1 = m01;
        float P2 = m01*cc2;
        float P3 = m0123;
        float P4 = m0123*cc4;
        float P5 = m0123*m45;
        float P6 = m0123*(m45*cc6);
        float P7 = m0123*m4567;
        float E0 = (cc1*m23)*m4567;          // prod c1..c7

        float t0v = p0 ? P1 : E0;
        float t1v = p0 ? P3 : P2;
        float t2v = p0 ? P5 : P4;
        float t3v = p0 ? P7 : P6;
        float u0 = p1 ? t1v : t0v;
        float u1 = p1 ? t3v : t2v;
        float e  = p2 ? u1 : u0;             // <Z_wire> for own wire

        float act = fmaf(aMul, tanh_approx(e * aScl), aAdd);

        // --- cross-gate act butterfly: 3 shfls ---
        float a1 = __shfl_xor_sync(FULL, act, 8);    // gate g^1
        float a2 = __shfl_xor_sync(FULL, act, 16);   // gate g^2
        float a3 = __shfl_xor_sync(FULL, a1, 16);    // gate g^3

        // select f/i/u/o by value index j = g ^ target  (v0=act,v1=a1,v2=a2,v3=a3)
        float vf = gb1 ? (gb0 ? a3  : a2) : (gb0 ? a1  : act);
        float vi = gb1 ? (gb0 ? a2  : a3) : (gb0 ? act : a1);
        float vu = gb1 ? (gb0 ? a1  : act) : (gb0 ? a3  : a2);
        float vo = gb1 ? (gb0 ? act : a1) : (gb0 ? a2  : a3);

        cstate = fmaf(vf, cstate, vi * vu);
        hv     = vo * tanh_approx(cstate);

        *st = hv;                             // branch-free store
        st += sstr;
    }

    if (lane < 8) {
        const size_t outs_sz = (size_t)T_SEQ * BATCH * NQ;
        out[outs_sz + (size_t)row * NQ + wire] = hv;                           // final hx
        out[outs_sz + (size_t)BATCH * NQ + (size_t)row * NQ + wire] = cstate;  // final cx
    }
}

// ---------------------------------------------------------------------------
// Launch
// ---------------------------------------------------------------------------
extern "C" void kernel_launch(void* const* d_in, const int* in_sizes, int n_in,
                              void* d_out, int out_size)
{
    const float* x   = (const float*)d_in[0];
    const float* Wf  = (const float*)d_in[1];
    const float* bf  = (const float*)d_in[2];
    const float* thf = (const float*)d_in[3];
    const float* Wi  = (const float*)d_in[4];
    const float* bi  = (const float*)d_in[5];
    const float* thi = (const float*)d_in[6];
    const float* Wu  = (const float*)d_in[7];
    const float* bu  = (const float*)d_in[8];
    const float* thu = (const float*)d_in[9];
    const float* Wo  = (const float*)d_in[10];
    const float* bo  = (const float*)d_in[11];
    const float* tho = (const float*)d_in[12];
    float* out = (float*)d_out;

    qlstm_gemm<<<(T_SEQ * BATCH) / 128, 128>>>(x, Wf, Wi, Wu, Wo);
    qlstm_recurrent<<<BATCH / 4, 128>>>(Wf, bf, thf, Wi, bi, thi,
                                        Wu, bu, thu, Wo, bo, tho, out);
}